// round 1
// baseline (speedup 1.0000x reference)
#include <cuda_runtime.h>

// Problem constants (fixed by setup_inputs)
#define BB   2
#define NN   16384
#define CC   64
#define SS   4096
#define KK   32
#define R2   0.16f
#define CIN  67
#define H3   128

#define OUT_F (BB*SS*3)              /* 24576  : new_xyz region     */
#define OUT_I (OUT_F + BB*H3*SS)     /* 1073152: samp_idx region    */

// Scratch (device globals — no allocation allowed)
__device__ float4 g_pts[BB*NN];          // x,y,z,|p|^2
__device__ float  g_featT[BB*NN*CC];     // [B][N][C]
__device__ int    g_idx[BB*SS*KK];       // ball query result

// ---------------------------------------------------------------------------
// Pack xyz into float4 SoA with precomputed squared norm
__global__ void k_prep(const float* __restrict__ xyz) {
    int i = blockIdx.x * blockDim.x + threadIdx.x;
    if (i < BB*NN) {
        float x = xyz[3*i+0], y = xyz[3*i+1], z = xyz[3*i+2];
        g_pts[i] = make_float4(x, y, z, fmaf(z, z, fmaf(y, y, x*x)));
    }
}

// ---------------------------------------------------------------------------
// Transpose features [B,C,N] -> [B,N,C]  (tiled, conflict-free)
__global__ void k_trans(const float* __restrict__ feat) {
    __shared__ float tile[32][33];
    int b  = blockIdx.z;
    int n0 = blockIdx.x * 32, c0 = blockIdx.y * 32;
    int tx = threadIdx.x, ty = threadIdx.y;
    #pragma unroll
    for (int i = ty; i < 32; i += 8)
        tile[i][tx] = feat[(size_t)b*CC*NN + (size_t)(c0+i)*NN + (n0+tx)];
    __syncthreads();
    #pragma unroll
    for (int i = ty; i < 32; i += 8)
        g_featT[(size_t)b*NN*CC + (size_t)(n0+i)*CC + (c0+tx)] = tile[tx][i];
}

// ---------------------------------------------------------------------------
// new_xyz copy + samp_idx (as float, concatenated-output convention)
__global__ void k_outs(const float* __restrict__ xyz, float* __restrict__ out) {
    int i = blockIdx.x * blockDim.x + threadIdx.x;
    if (i < BB*SS) {
        int b = i / SS, s = i % SS;
        out[3*i+0] = xyz[(size_t)(b*NN+s)*3 + 0];
        out[3*i+1] = xyz[(size_t)(b*NN+s)*3 + 1];
        out[3*i+2] = xyz[(size_t)(b*NN+s)*3 + 2];
        out[OUT_I + i] = (float)s;
    }
}

// ---------------------------------------------------------------------------
// Ball query: one warp per centroid. Ordered scan; ballot+popc assigns the
// first KK in-index-order hits; early exit when full. Replicates reference
// semantics: d2 = |c|^2 + |p|^2 - 2 c.p ; fill empty slots with first hit (0
// if none).
__global__ void k_ball() {
    __shared__ int sbuf[8][KK];
    int w    = threadIdx.x >> 5;
    int lane = threadIdx.x & 31;
    int gw   = blockIdx.x * 8 + w;          // centroid id in [0, BB*SS)
    int b    = gw / SS, s = gw % SS;
    int base0 = b * NN;
    float4 c4 = g_pts[base0 + s];
    unsigned lmask = (1u << lane) - 1u;
    int cnt = 0;
    for (int base = 0; base < NN; base += 32) {
        float4 p = g_pts[base0 + base + lane];
        float d2 = c4.w + p.w - 2.0f * (c4.x*p.x + c4.y*p.y + c4.z*p.z);
        bool hit = d2 < R2;
        unsigned m = __ballot_sync(0xffffffffu, hit);
        if (hit) {
            int pos = cnt + __popc(m & lmask);
            if (pos < KK) sbuf[w][pos] = base + lane;
        }
        cnt += __popc(m);
        if (cnt >= KK) break;
    }
    __syncwarp();
    int v;
    if (cnt == 0) v = 0;
    else {
        int first = sbuf[w][0];
        v = (lane < cnt) ? sbuf[w][lane] : first;
    }
    g_idx[gw*KK + lane] = v;
}

// ---------------------------------------------------------------------------
// Fused gather + 3-layer MLP + max-pool. One 128-thread block per centroid
// iteration (persistent grid). All weights in dynamic smem (66.5 KB); h
// buffers padded to stride 68 for conflict-free LDS; register tiles keep
// LDS traffic below crossbar rate so FFMA is the binding pipe.
__global__ void __launch_bounds__(128) k_mlp(
    const float* __restrict__ W1, const float* __restrict__ b1,
    const float* __restrict__ W2, const float* __restrict__ b2,
    const float* __restrict__ W3, const float* __restrict__ b3,
    float* __restrict__ out)
{
    extern __shared__ float sm[];
    float* sW1  = sm;                 // 67*64  = 4288
    float* sW2  = sW1 + 4288;         // 64*64  = 4096
    float* sW3  = sW2 + 4096;         // 64*128 = 8192
    float* sb1  = sW3 + 8192;         // 64
    float* sb2  = sb1 + 64;           // 64
    float* sb3  = sb2 + 64;           // 128
    float* bufA = sb3 + 128;          // 32*68 = 2176
    float* bufB = bufA + 2176;        // 32*68 = 2176
    float* red  = bufB + 2176;        // 8*128 = 1024
    const int tid = threadIdx.x;

    for (int i = tid; i < 4288; i += 128) sW1[i] = W1[i];
    for (int i = tid; i < 4096; i += 128) sW2[i] = W2[i];
    for (int i = tid; i < 8192; i += 128) sW3[i] = W3[i];
    if (tid < 64) { sb1[tid] = b1[tid]; sb2[tid] = b2[tid]; }
    sb3[tid] = b3[tid];
    __syncthreads();

    const int dg = tid & 15;          // d-lane group (0..15)
    const int kg = tid >> 4;          // k group     (0..7)
    const int kq = tid >> 2;          // gather: k   (0..31)
    const int c0 = tid & 3;           // gather: lane within k

    for (int cent = blockIdx.x; cent < BB*SS; cent += gridDim.x) {
        const int b  = cent >> 12;          // /SS
        const int s  = cent & (SS-1);
        const int bN = b * NN;

        // ---- gather g[k][0:67] = [dxyz | features] into bufA ----
        {
            int n = g_idx[cent*KK + kq];
            float4 p   = g_pts[bN + n];
            float4 ctr = g_pts[bN + s];
            if      (c0 == 0) bufA[kq*68 + 0] = p.x - ctr.x;
            else if (c0 == 1) bufA[kq*68 + 1] = p.y - ctr.y;
            else if (c0 == 2) bufA[kq*68 + 2] = p.z - ctr.z;
            const float* fr = g_featT + (size_t)(bN + n) * CC;
            #pragma unroll
            for (int i2 = 0; i2 < 16; i2++) {
                int f = c0 + 4*i2;
                bufA[kq*68 + 3 + f] = fr[f];
            }
        }
        __syncthreads();

        // ---- layer 1: bufA(67) -> bufB(64), relu ----
        {
            float acc[4][4];
            #pragma unroll
            for (int i = 0; i < 4; i++)
                #pragma unroll
                for (int j = 0; j < 4; j++) acc[i][j] = sb1[dg + 16*j];
            for (int c = 0; c < CIN; c++) {
                float wv[4];
                #pragma unroll
                for (int j = 0; j < 4; j++) wv[j] = sW1[c*64 + dg + 16*j];
                #pragma unroll
                for (int i = 0; i < 4; i++) {
                    float gv = bufA[(kg + 8*i)*68 + c];
                    #pragma unroll
                    for (int j = 0; j < 4; j++)
                        acc[i][j] = fmaf(gv, wv[j], acc[i][j]);
                }
            }
            #pragma unroll
            for (int i = 0; i < 4; i++)
                #pragma unroll
                for (int j = 0; j < 4; j++)
                    bufB[(kg + 8*i)*68 + dg + 16*j] = fmaxf(acc[i][j], 0.f);
        }
        __syncthreads();

        // ---- layer 2: bufB(64) -> bufA(64), relu ----
        {
            float acc[4][4];
            #pragma unroll
            for (int i = 0; i < 4; i++)
                #pragma unroll
                for (int j = 0; j < 4; j++) acc[i][j] = sb2[dg + 16*j];
            for (int c = 0; c < 64; c++) {
                float wv[4];
                #pragma unroll
                for (int j = 0; j < 4; j++) wv[j] = sW2[c*64 + dg + 16*j];
                #pragma unroll
                for (int i = 0; i < 4; i++) {
                    float gv = bufB[(kg + 8*i)*68 + c];
                    #pragma unroll
                    for (int j = 0; j < 4; j++)
                        acc[i][j] = fmaf(gv, wv[j], acc[i][j]);
                }
            }
            #pragma unroll
            for (int i = 0; i < 4; i++)
                #pragma unroll
                for (int j = 0; j < 4; j++)
                    bufA[(kg + 8*i)*68 + dg + 16*j] = fmaxf(acc[i][j], 0.f);
        }
        __syncthreads();

        // ---- layer 3: bufA(64) -> 128 outs, relu, partial max over 4 k ----
        {
            float acc[4][8];
            #pragma unroll
            for (int i = 0; i < 4; i++)
                #pragma unroll
                for (int j = 0; j < 8; j++) acc[i][j] = sb3[dg + 16*j];
            for (int c = 0; c < 64; c++) {
                float wv[8];
                #pragma unroll
                for (int j = 0; j < 8; j++) wv[j] = sW3[c*128 + dg + 16*j];
                #pragma unroll
                for (int i = 0; i < 4; i++) {
                    float gv = bufA[(kg + 8*i)*68 + c];
                    #pragma unroll
                    for (int j = 0; j < 8; j++)
                        acc[i][j] = fmaf(gv, wv[j], acc[i][j]);
                }
            }
            #pragma unroll
            for (int j = 0; j < 8; j++) {
                float m = fmaxf(acc[0][j], 0.f);
                #pragma unroll
                for (int i = 1; i < 4; i++) m = fmaxf(m, fmaxf(acc[i][j], 0.f));
                red[kg*128 + dg + 16*j] = m;
            }
        }
        __syncthreads();

        // ---- final max across the 8 k-groups; write new_features [B,128,S] ----
        {
            float m = red[tid];
            #pragma unroll
            for (int g = 1; g < 8; g++) m = fmaxf(m, red[g*128 + tid]);
            out[OUT_F + (size_t)b*H3*SS + (size_t)tid*SS + s] = m;
        }
        __syncthreads();
    }
}

// ---------------------------------------------------------------------------
extern "C" void kernel_launch(void* const* d_in, const int* in_sizes, int n_in,
                              void* d_out, int out_size) {
    (void)in_sizes; (void)n_in; (void)out_size;
    const float* xyz  = (const float*)d_in[0];
    const float* feat = (const float*)d_in[1];
    const float* W1   = (const float*)d_in[2];
    const float* b1   = (const float*)d_in[3];
    const float* W2   = (const float*)d_in[4];
    const float* b2   = (const float*)d_in[5];
    const float* W3   = (const float*)d_in[6];
    const float* b3   = (const float*)d_in[7];
    float* out = (float*)d_out;

    const int smem_mlp = 22208 * 4;   // 88,832 B
    cudaFuncSetAttribute(k_mlp, cudaFuncAttributeMaxDynamicSharedMemorySize, smem_mlp);

    k_prep<<<(BB*NN + 255)/256, 256>>>(xyz);
    k_trans<<<dim3(NN/32, CC/32, BB), dim3(32, 8)>>>(feat);
    k_outs<<<(BB*SS + 255)/256, 256>>>(xyz, out);
    k_ball<<<(BB*SS)/8, 256>>>();
    k_mlp<<<296, 128, smem_mlp>>>(W1, b1, W2, b2, W3, b3, out);
}

// round 2
// speedup vs baseline: 1.4375x; 1.4375x over previous
#include <cuda_runtime.h>

// Problem constants (fixed by setup_inputs)
#define BB   2
#define NN   16384
#define CC   64
#define SS   4096
#define KK   32
#define R2   0.16f
#define CIN  67
#define H3   128

#define OUT_F (BB*SS*3)              /* 24576  : new_xyz region     */
#define OUT_I (OUT_F + BB*H3*SS)     /* 1073152: samp_idx region    */

// Scratch (device globals — no allocation allowed)
__device__ float4 g_pts[BB*NN];          // x,y,z,|p|^2
__device__ float  g_featT[BB*NN*CC];     // [B][N][C]
__device__ int    g_idx[BB*SS*KK];       // ball query result

// ---- packed f32x2 helpers (FFMA2: 2x fp32 FMA rate, PTX-only) -------------
typedef unsigned long long ull;
__device__ __forceinline__ ull pk2(float lo, float hi) {
    ull r; asm("mov.b64 %0,{%1,%2};" : "=l"(r) : "f"(lo), "f"(hi)); return r;
}
__device__ __forceinline__ void upk2(ull v, float& lo, float& hi) {
    asm("mov.b64 {%0,%1},%2;" : "=f"(lo), "=f"(hi) : "l"(v));
}
__device__ __forceinline__ ull ffma2(ull a, ull b, ull c) {
    ull d; asm("fma.rn.f32x2 %0,%1,%2,%3;" : "=l"(d) : "l"(a), "l"(b), "l"(c));
    return d;
}
__device__ __forceinline__ ull ldp(const float* p) {   // aligned smem pair
    return *reinterpret_cast<const ull*>(p);
}

// ---------------------------------------------------------------------------
// Pack xyz into float4 SoA with precomputed squared norm
__global__ void k_prep(const float* __restrict__ xyz) {
    int i = blockIdx.x * blockDim.x + threadIdx.x;
    if (i < BB*NN) {
        float x = xyz[3*i+0], y = xyz[3*i+1], z = xyz[3*i+2];
        g_pts[i] = make_float4(x, y, z, fmaf(z, z, fmaf(y, y, x*x)));
    }
}

// ---------------------------------------------------------------------------
// Transpose features [B,C,N] -> [B,N,C]  (tiled, conflict-free)
__global__ void k_trans(const float* __restrict__ feat) {
    __shared__ float tile[32][33];
    int b  = blockIdx.z;
    int n0 = blockIdx.x * 32, c0 = blockIdx.y * 32;
    int tx = threadIdx.x, ty = threadIdx.y;
    #pragma unroll
    for (int i = ty; i < 32; i += 8)
        tile[i][tx] = feat[(size_t)b*CC*NN + (size_t)(c0+i)*NN + (n0+tx)];
    __syncthreads();
    #pragma unroll
    for (int i = ty; i < 32; i += 8)
        g_featT[(size_t)b*NN*CC + (size_t)(n0+i)*CC + (c0+tx)] = tile[tx][i];
}

// ---------------------------------------------------------------------------
// new_xyz copy + samp_idx (as float, concatenated-output convention)
__global__ void k_outs(const float* __restrict__ xyz, float* __restrict__ out) {
    int i = blockIdx.x * blockDim.x + threadIdx.x;
    if (i < BB*SS) {
        int b = i / SS, s = i % SS;
        out[3*i+0] = xyz[(size_t)(b*NN+s)*3 + 0];
        out[3*i+1] = xyz[(size_t)(b*NN+s)*3 + 1];
        out[3*i+2] = xyz[(size_t)(b*NN+s)*3 + 2];
        out[OUT_I + i] = (float)s;
    }
}

// ---------------------------------------------------------------------------
// Ball query: one warp per centroid. Unrolled x4 for MLP=4 (latency-bound in
// R1: issue=18%). Ordered scan; ballot+popc assigns the first KK
// in-index-order hits; early exit every 128 points. Replicates reference
// semantics exactly.
__global__ void k_ball() {
    __shared__ int sbuf[8][KK];
    int w    = threadIdx.x >> 5;
    int lane = threadIdx.x & 31;
    int gw   = blockIdx.x * 8 + w;          // centroid id in [0, BB*SS)
    int b    = gw / SS, s = gw % SS;
    int base0 = b * NN;
    float4 c4 = g_pts[base0 + s];
    unsigned lmask = (1u << lane) - 1u;
    int cnt = 0;
    for (int base = 0; base < NN; base += 128) {
        // 4 independent loads issued up front (MLP=4)
        float4 p0 = g_pts[base0 + base + lane];
        float4 p1 = g_pts[base0 + base + 32  + lane];
        float4 p2 = g_pts[base0 + base + 64  + lane];
        float4 p3 = g_pts[base0 + base + 96  + lane];
        float d0 = c4.w + p0.w - 2.0f*(c4.x*p0.x + c4.y*p0.y + c4.z*p0.z);
        float d1 = c4.w + p1.w - 2.0f*(c4.x*p1.x + c4.y*p1.y + c4.z*p1.z);
        float d2 = c4.w + p2.w - 2.0f*(c4.x*p2.x + c4.y*p2.y + c4.z*p2.z);
        float d3 = c4.w + p3.w - 2.0f*(c4.x*p3.x + c4.y*p3.y + c4.z*p3.z);
        unsigned m0 = __ballot_sync(0xffffffffu, d0 < R2);
        unsigned m1 = __ballot_sync(0xffffffffu, d1 < R2);
        unsigned m2 = __ballot_sync(0xffffffffu, d2 < R2);
        unsigned m3 = __ballot_sync(0xffffffffu, d3 < R2);
        if (m0 & (1u << lane)) {
            int pos = cnt + __popc(m0 & lmask);
            if (pos < KK) sbuf[w][pos] = base + lane;
        }
        cnt += __popc(m0);
        if (m1 & (1u << lane)) {
            int pos = cnt + __popc(m1 & lmask);
            if (pos < KK) sbuf[w][pos] = base + 32 + lane;
        }
        cnt += __popc(m1);
        if (m2 & (1u << lane)) {
            int pos = cnt + __popc(m2 & lmask);
            if (pos < KK) sbuf[w][pos] = base + 64 + lane;
        }
        cnt += __popc(m2);
        if (m3 & (1u << lane)) {
            int pos = cnt + __popc(m3 & lmask);
            if (pos < KK) sbuf[w][pos] = base + 96 + lane;
        }
        cnt += __popc(m3);
        if (cnt >= KK) break;
    }
    __syncwarp();
    int v;
    if (cnt == 0) v = 0;
    else {
        int first = sbuf[w][0];
        v = (lane < KK) ? ((lane < cnt) ? sbuf[w][lane] : first) : first;
        if (lane >= cnt) v = first;
        else v = sbuf[w][lane < KK ? lane : 0];
        // simple, exact: first cnt slots valid, rest = first hit
        v = (lane < cnt && lane < KK) ? sbuf[w][lane] : first;
    }
    g_idx[gw*KK + lane] = v;
}

// ---------------------------------------------------------------------------
// Fused gather + 3-layer MLP + max-pool, FFMA2 (f32x2) math.
// 128 threads/block, persistent grid. Weights in smem; h buffers stride 68.
// Thread tiling: kg=tid>>4 owns k in {kg,kg+8,kg+16,kg+24};
// dg=tid&15 owns channel pairs d = 2*dg + 32*j.
__global__ void __launch_bounds__(128) k_mlp(
    const float* __restrict__ W1, const float* __restrict__ b1,
    const float* __restrict__ W2, const float* __restrict__ b2,
    const float* __restrict__ W3, const float* __restrict__ b3,
    float* __restrict__ out)
{
    extern __shared__ float sm[];
    float* sW1  = sm;                 // 67*64  = 4288
    float* sW2  = sW1 + 4288;         // 64*64  = 4096
    float* sW3  = sW2 + 4096;         // 64*128 = 8192
    float* sb1  = sW3 + 8192;         // 64
    float* sb2  = sb1 + 64;           // 64
    float* sb3  = sb2 + 64;           // 128
    float* bufA = sb3 + 128;          // 32*68 = 2176
    float* bufB = bufA + 2176;        // 32*68 = 2176
    float* red  = bufB + 2176;        // 8*128 = 1024
    const int tid = threadIdx.x;

    for (int i = tid; i < 4288; i += 128) sW1[i] = W1[i];
    for (int i = tid; i < 4096; i += 128) sW2[i] = W2[i];
    for (int i = tid; i < 8192; i += 128) sW3[i] = W3[i];
    if (tid < 64) { sb1[tid] = b1[tid]; sb2[tid] = b2[tid]; }
    sb3[tid] = b3[tid];
    __syncthreads();

    const int dg = tid & 15;          // channel-pair lane (0..15)
    const int kg = tid >> 4;          // k group (0..7)
    const int kq = tid >> 2;          // gather: k (0..31)
    const int c0 = tid & 3;           // gather: lane within k

    for (int cent = blockIdx.x; cent < BB*SS; cent += gridDim.x) {
        const int b  = cent >> 12;          // /SS
        const int s  = cent & (SS-1);
        const int bN = b * NN;

        // ---- gather g[k][0:67] = [dxyz | features] into bufA ----
        {
            int n = g_idx[cent*KK + kq];
            float4 p   = g_pts[bN + n];
            float4 ctr = g_pts[bN + s];
            if      (c0 == 0) bufA[kq*68 + 0] = p.x - ctr.x;
            else if (c0 == 1) bufA[kq*68 + 1] = p.y - ctr.y;
            else if (c0 == 2) bufA[kq*68 + 2] = p.z - ctr.z;
            const float* fr = g_featT + (size_t)(bN + n) * CC;
            #pragma unroll
            for (int i2 = 0; i2 < 16; i2++) {
                int f = c0 + 4*i2;
                bufA[kq*68 + 3 + f] = fr[f];
            }
        }
        __syncthreads();

        // ---- layer 1: bufA(67) -> bufB(64), relu  [FFMA2] ----
        {
            ull acc[4][2];
            ull bi0 = ldp(sb1 + 2*dg), bi1 = ldp(sb1 + 2*dg + 32);
            #pragma unroll
            for (int i = 0; i < 4; i++) { acc[i][0] = bi0; acc[i][1] = bi1; }
            for (int c = 0; c < CIN; c++) {
                ull wv0 = ldp(sW1 + c*64 + 2*dg);
                ull wv1 = ldp(sW1 + c*64 + 2*dg + 32);
                #pragma unroll
                for (int i = 0; i < 4; i++) {
                    float gv = bufA[(kg + 8*i)*68 + c];
                    ull gg = pk2(gv, gv);
                    acc[i][0] = ffma2(gg, wv0, acc[i][0]);
                    acc[i][1] = ffma2(gg, wv1, acc[i][1]);
                }
            }
            #pragma unroll
            for (int i = 0; i < 4; i++)
                #pragma unroll
                for (int j = 0; j < 2; j++) {
                    float lo, hi; upk2(acc[i][j], lo, hi);
                    float2 v = make_float2(fmaxf(lo, 0.f), fmaxf(hi, 0.f));
                    *(float2*)&bufB[(kg + 8*i)*68 + 2*dg + 32*j] = v;
                }
        }
        __syncthreads();

        // ---- layer 2: bufB(64) -> bufA(64), relu  [FFMA2] ----
        {
            ull acc[4][2];
            ull bi0 = ldp(sb2 + 2*dg), bi1 = ldp(sb2 + 2*dg + 32);
            #pragma unroll
            for (int i = 0; i < 4; i++) { acc[i][0] = bi0; acc[i][1] = bi1; }
            for (int c = 0; c < 64; c++) {
                ull wv0 = ldp(sW2 + c*64 + 2*dg);
                ull wv1 = ldp(sW2 + c*64 + 2*dg + 32);
                #pragma unroll
                for (int i = 0; i < 4; i++) {
                    float gv = bufB[(kg + 8*i)*68 + c];
                    ull gg = pk2(gv, gv);
                    acc[i][0] = ffma2(gg, wv0, acc[i][0]);
                    acc[i][1] = ffma2(gg, wv1, acc[i][1]);
                }
            }
            #pragma unroll
            for (int i = 0; i < 4; i++)
                #pragma unroll
                for (int j = 0; j < 2; j++) {
                    float lo, hi; upk2(acc[i][j], lo, hi);
                    float2 v = make_float2(fmaxf(lo, 0.f), fmaxf(hi, 0.f));
                    *(float2*)&bufA[(kg + 8*i)*68 + 2*dg + 32*j] = v;
                }
        }
        __syncthreads();

        // ---- layer 3: bufA(64) -> 128 outs, relu, partial max over 4 k [FFMA2] ----
        {
            ull acc[4][4];
            #pragma unroll
            for (int j = 0; j < 4; j++) {
                ull bi = ldp(sb3 + 2*dg + 32*j);
                #pragma unroll
                for (int i = 0; i < 4; i++) acc[i][j] = bi;
            }
            for (int c = 0; c < 64; c++) {
                ull wv[4];
                #pragma unroll
                for (int j = 0; j < 4; j++) wv[j] = ldp(sW3 + c*128 + 2*dg + 32*j);
                #pragma unroll
                for (int i = 0; i < 4; i++) {
                    float gv = bufA[(kg + 8*i)*68 + c];
                    ull gg = pk2(gv, gv);
                    #pragma unroll
                    for (int j = 0; j < 4; j++)
                        acc[i][j] = ffma2(gg, wv[j], acc[i][j]);
                }
            }
            #pragma unroll
            for (int j = 0; j < 4; j++) {
                float l0, h0, l1, h1, l2, h2, l3, h3;
                upk2(acc[0][j], l0, h0); upk2(acc[1][j], l1, h1);
                upk2(acc[2][j], l2, h2); upk2(acc[3][j], l3, h3);
                float ml = fmaxf(fmaxf(fmaxf(l0,0.f), fmaxf(l1,0.f)),
                                 fmaxf(fmaxf(l2,0.f), fmaxf(l3,0.f)));
                float mh = fmaxf(fmaxf(fmaxf(h0,0.f), fmaxf(h1,0.f)),
                                 fmaxf(fmaxf(h2,0.f), fmaxf(h3,0.f)));
                *(float2*)&red[kg*128 + 2*dg + 32*j] = make_float2(ml, mh);
            }
        }
        __syncthreads();

        // ---- final max across the 8 k-groups; write new_features [B,128,S] ----
        {
            float m = red[tid];
            #pragma unroll
            for (int g = 1; g < 8; g++) m = fmaxf(m, red[g*128 + tid]);
            out[OUT_F + (size_t)b*H3*SS + (size_t)tid*SS + s] = m;
        }
        __syncthreads();
    }
}

// ---------------------------------------------------------------------------
extern "C" void kernel_launch(void* const* d_in, const int* in_sizes, int n_in,
                              void* d_out, int out_size) {
    (void)in_sizes; (void)n_in; (void)out_size;
    const float* xyz  = (const float*)d_in[0];
    const float* feat = (const float*)d_in[1];
    const float* W1   = (const float*)d_in[2];
    const float* b1   = (const float*)d_in[3];
    const float* W2   = (const float*)d_in[4];
    const float* b2   = (const float*)d_in[5];
    const float* W3   = (const float*)d_in[6];
    const float* b3   = (const float*)d_in[7];
    float* out = (float*)d_out;

    const int smem_mlp = 22208 * 4;   // 88,832 B
    cudaFuncSetAttribute(k_mlp, cudaFuncAttributeMaxDynamicSharedMemorySize, smem_mlp);

    k_prep<<<(BB*NN + 255)/256, 256>>>(xyz);
    k_trans<<<dim3(NN/32, CC/32, BB), dim3(32, 8)>>>(feat);
    k_outs<<<(BB*SS + 255)/256, 256>>>(xyz, out);
    k_ball<<<(BB*SS)/8, 256>>>();
    k_mlp<<<296, 128, smem_mlp>>>(W1, b1, W2, b2, W3, b3, out);
}